// round 1
// baseline (speedup 1.0000x reference)
#include <cuda_runtime.h>

#define THREADS 128
#define EPT 2   // batch elements per thread

__device__ __forceinline__ float sigm(float x) {
    return __fdividef(1.0f, 1.0f + __expf(-x));
}
__device__ __forceinline__ float tanh_(float x) {
    return __fdividef(2.0f, 1.0f + __expf(-2.0f * x)) - 1.0f;
}

struct __align__(16) SW {
    float Wih[64 * 4];    // main LSTM input weights  [64][4]
    float Whh[64 * 16];   // main LSTM hidden weights [64][16]
    float Weih[64 * 4];   // encoder LSTM input weights
    float Wehh[64 * 16];  // encoder LSTM hidden weights
    float B[64];          // b_ih + b_hh (main)
    float Be[64];         // be_ih + be_hh (encoder)
    float W1[8 * 16];     // mlp layer 1
    float W2[4 * 8];      // mlp layer 2
    float Wenc[4 * 16];   // final projection
    float Wl[12 * 13];    // linear_layer weight
    float B1[8];
    float B2[4];
    float Benc[4];
    float Bl[12];
    float g[8];           // Wg[0..2], bg, Wg2[0..2], bg2
};

// One LSTM cell step for 2 batch elements held by this thread.
// Weights come from SMEM via broadcast float4 loads.
__device__ __forceinline__ void cell2(
    const float4* __restrict__ wi4,   // [64] rows (4 floats each)
    const float4* __restrict__ wh4,   // [64][4] rows of float4
    const float* __restrict__ bias,   // [64]
    const float (&za)[2][4],
    float (&h)[2][16], float (&c)[2][16])
{
    float hn[2][16];
#pragma unroll 4
    for (int u = 0; u < 16; u++) {
        float acc[2][4];
#pragma unroll
        for (int e = 0; e < 2; e++) {
            acc[e][0] = bias[u];
            acc[e][1] = bias[u + 16];
            acc[e][2] = bias[u + 32];
            acc[e][3] = bias[u + 48];
        }
        // input contribution: gate rows u, u+16, u+32, u+48
#pragma unroll
        for (int gi = 0; gi < 4; gi++) {
            float4 w = wi4[u + 16 * gi];
#pragma unroll
            for (int e = 0; e < 2; e++)
                acc[e][gi] += za[e][0] * w.x + za[e][1] * w.y +
                              za[e][2] * w.z + za[e][3] * w.w;
        }
        // hidden contribution
#pragma unroll
        for (int gi = 0; gi < 4; gi++) {
#pragma unroll
            for (int q = 0; q < 4; q++) {
                float4 w = wh4[(u + 16 * gi) * 4 + q];
#pragma unroll
                for (int e = 0; e < 2; e++)
                    acc[e][gi] += h[e][4 * q + 0] * w.x + h[e][4 * q + 1] * w.y +
                                  h[e][4 * q + 2] * w.z + h[e][4 * q + 3] * w.w;
            }
        }
#pragma unroll
        for (int e = 0; e < 2; e++) {
            float ci = sigm(acc[e][0]) * tanh_(acc[e][2]);
            float cf = sigm(acc[e][1]);
            c[e][u] = cf * c[e][u] + ci;
            hn[e][u] = sigm(acc[e][3]) * tanh_(c[e][u]);
        }
    }
#pragma unroll
    for (int e = 0; e < 2; e++)
#pragma unroll
        for (int k = 0; k < 16; k++) h[e][k] = hn[e][k];
}

__global__ void __launch_bounds__(THREADS, 2) stae_kernel(
    const float* __restrict__ x, const float* __restrict__ z,
    const float* __restrict__ W_ih, const float* __restrict__ W_hh,
    const float* __restrict__ b_ih, const float* __restrict__ b_hh,
    const float* __restrict__ mW1, const float* __restrict__ mb1,
    const float* __restrict__ mW2, const float* __restrict__ mb2,
    const float* __restrict__ Wg, const float* __restrict__ bg,
    const float* __restrict__ Wg2, const float* __restrict__ bg2,
    const float* __restrict__ Wl, const float* __restrict__ bl,
    const float* __restrict__ We_ih, const float* __restrict__ We_hh,
    const float* __restrict__ be_ih, const float* __restrict__ be_hh,
    const float* __restrict__ Wenc, const float* __restrict__ benc,
    float* __restrict__ out, int B)
{
    __shared__ SW s;
    const int tid = threadIdx.x;

    for (int i = tid; i < 256; i += THREADS) { s.Wih[i] = W_ih[i]; s.Weih[i] = We_ih[i]; }
    for (int i = tid; i < 1024; i += THREADS) { s.Whh[i] = W_hh[i]; s.Wehh[i] = We_hh[i]; }
    for (int i = tid; i < 64; i += THREADS) {
        s.B[i] = b_ih[i] + b_hh[i];
        s.Be[i] = be_ih[i] + be_hh[i];
        s.Wenc[i] = Wenc[i];
    }
    for (int i = tid; i < 156; i += THREADS) s.Wl[i] = Wl[i];
    if (tid < 128) s.W1[tid] = mW1[tid];
    if (tid < 32)  s.W2[tid] = mW2[tid];
    if (tid < 12)  s.Bl[tid] = bl[tid];
    if (tid < 8)   s.B1[tid] = mb1[tid];
    if (tid < 4)   { s.B2[tid] = mb2[tid]; s.Benc[tid] = benc[tid]; }
    if (tid < 3)   { s.g[tid] = Wg[tid]; s.g[4 + tid] = Wg2[tid]; }
    if (tid == 3)  { s.g[3] = bg[0]; s.g[7] = bg2[0]; }
    __syncthreads();

    const int b0 = blockIdx.x * (THREADS * EPT) + tid;
    if (b0 >= B) return;
    const int b1 = b0 + THREADS;
    const int b1c = (b1 < B) ? b1 : b0;   // clamp: duplicate work, guarded writes

    const float4* Wih4 = (const float4*)s.Wih;
    const float4* Whh4 = (const float4*)s.Whh;
    const float4* Weih4 = (const float4*)s.Weih;
    const float4* Wehh4 = (const float4*)s.Wehh;

    const float* zb0 = z + (size_t)b0 * 48;
    const float* zb1 = z + (size_t)b1c * 48;

    float h[2][16], c[2][16];
#pragma unroll
    for (int e = 0; e < 2; e++)
#pragma unroll
        for (int k = 0; k < 16; k++) { h[e][k] = 0.f; c[e][k] = 0.f; }

    // ---------------- main LSTM over z (only last h needed) ----------------
    for (int t = 0; t < 12; t++) {
        float4 z0 = *(const float4*)(zb0 + t * 4);
        float4 z1 = *(const float4*)(zb1 + t * 4);
        float za[2][4] = {{z0.x, z0.y, z0.z, z0.w}, {z1.x, z1.y, z1.z, z1.w}};
        cell2(Wih4, Whh4, s.B, za, h, c);
    }

    // ---------------- middle: mlp -> gcn2 -> v_out; stage x + v_out locally ----
    float xl[2][48];    // x row (reshape-faithful flat view), local mem
    float vout[2][48];  // v_out[n][t] at index n*12+t, local mem
#pragma unroll
    for (int e = 0; e < 2; e++) {
        float m1[8];
#pragma unroll
        for (int j = 0; j < 8; j++) {
            float a = s.B1[j];
#pragma unroll
            for (int k = 0; k < 16; k++) a += h[e][k] * s.W1[j * 16 + k];
            m1[j] = fmaxf(a, 0.f);
        }
        float mo[4];
#pragma unroll
        for (int n = 0; n < 4; n++) {
            float a = s.B2[n];
#pragma unroll
            for (int j = 0; j < 8; j++) a += m1[j] * s.W2[n * 8 + j];
            mo[n] = a;
        }
        // GCN2 diffusion on mlp output (path graph 0-1-2-3)
        float x1_0 = mo[1], x1_1 = mo[0] + mo[2], x1_2 = mo[1] + mo[3], x1_3 = mo[2];
        float x2_0 = x1_1, x2_1 = x1_0 + x1_2, x2_2 = x1_1 + x1_3, x2_3 = x1_2;
        float w0 = s.g[4], w1 = s.g[5], w2 = s.g[6], bb = s.g[7];
        float mg[4];
        mg[0] = w0 * mo[0] + w1 * x1_0 + w2 * x2_0 + bb;
        mg[1] = w0 * mo[1] + w1 * x1_1 + w2 * x2_1 + bb;
        mg[2] = w0 * mo[2] + w1 * x1_2 + w2 * x2_2 + bb;
        mg[3] = w0 * mo[3] + w1 * x1_3 + w2 * x2_3 + bb;

        const float* xb = x + (size_t)((e == 0) ? b0 : b1c) * 48;
#pragma unroll
        for (int q = 0; q < 12; q++) {
            float4 v = *(const float4*)(xb + q * 4);
            xl[e][q * 4 + 0] = v.x; xl[e][q * 4 + 1] = v.y;
            xl[e][q * 4 + 2] = v.z; xl[e][q * 4 + 3] = v.w;
        }
        // v_out[n][t] = bl[t] + sum_k seq1[n][k]*Wl[t][k], seq1 = [x_r row n, mg[n]]
#pragma unroll
        for (int n = 0; n < 4; n++) {
#pragma unroll
            for (int tt = 0; tt < 12; tt++) {
                float a = s.Bl[tt] + mg[n] * s.Wl[tt * 13 + 12];
#pragma unroll
                for (int k = 0; k < 12; k++) a += xl[e][n * 12 + k] * s.Wl[tt * 13 + k];
                vout[e][n * 12 + tt] = a;
            }
        }
    }

    // ---------------- encoder LSTM over en = gcn(x) + gcn2(v_out) --------------
#pragma unroll
    for (int e = 0; e < 2; e++)
#pragma unroll
        for (int k = 0; k < 16; k++) { h[e][k] = 0.f; c[e][k] = 0.f; }

    const float gw0 = s.g[0], gw1 = s.g[1], gw2 = s.g[2], gb = s.g[3];
    const float qw0 = s.g[4], qw1 = s.g[5], qw2 = s.g[6], qb = s.g[7];

    for (int t = 0; t < 12; t++) {
        float en[2][4];
#pragma unroll
        for (int e = 0; e < 2; e++) {
            float i0 = xl[e][t],       i1 = xl[e][12 + t];
            float i2 = xl[e][24 + t],  i3 = xl[e][36 + t];
            float v0 = vout[e][t],      v1 = vout[e][12 + t];
            float v2 = vout[e][24 + t], v3 = vout[e][36 + t];
            float a1_0 = i1, a1_1 = i0 + i2, a1_2 = i1 + i3, a1_3 = i2;
            float a2_0 = a1_1, a2_1 = a1_0 + a1_2, a2_2 = a1_1 + a1_3, a2_3 = a1_2;
            float c1_0 = v1, c1_1 = v0 + v2, c1_2 = v1 + v3, c1_3 = v2;
            float c2_0 = c1_1, c2_1 = c1_0 + c1_2, c2_2 = c1_1 + c1_3, c2_3 = c1_2;
            en[e][0] = gw0 * i0 + gw1 * a1_0 + gw2 * a2_0 + gb
                     + qw0 * v0 + qw1 * c1_0 + qw2 * c2_0 + qb;
            en[e][1] = gw0 * i1 + gw1 * a1_1 + gw2 * a2_1 + gb
                     + qw0 * v1 + qw1 * c1_1 + qw2 * c2_1 + qb;
            en[e][2] = gw0 * i2 + gw1 * a1_2 + gw2 * a2_2 + gb
                     + qw0 * v2 + qw1 * c1_2 + qw2 * c2_2 + qb;
            en[e][3] = gw0 * i3 + gw1 * a1_3 + gw2 * a2_3 + gb
                     + qw0 * v3 + qw1 * c1_3 + qw2 * c2_3 + qb;
        }
        cell2(Weih4, Wehh4, s.Be, en, h, c);
    }

    // ---------------- final projection (only last step) + broadcast write ------
    float lp[2][4];
#pragma unroll
    for (int e = 0; e < 2; e++)
#pragma unroll
        for (int n = 0; n < 4; n++) {
            float a = s.Benc[n];
#pragma unroll
            for (int k = 0; k < 16; k++) a += h[e][k] * s.Wenc[n * 16 + k];
            lp[e][n] = a;
        }

    {
        float4* o0 = (float4*)(out + (size_t)b0 * 48);
#pragma unroll
        for (int j = 0; j < 12; j++) {
            float v = lp[0][j / 3];
            o0[j] = make_float4(v, v, v, v);
        }
        if (b1 < B) {
            float4* o1 = (float4*)(out + (size_t)b1 * 48);
#pragma unroll
            for (int j = 0; j < 12; j++) {
                float v = lp[1][j / 3];
                o1[j] = make_float4(v, v, v, v);
            }
        }
    }
}

extern "C" void kernel_launch(void* const* d_in, const int* in_sizes, int n_in,
                              void* d_out, int out_size)
{
    const float* x     = (const float*)d_in[0];
    const float* z     = (const float*)d_in[1];
    const float* W_ih  = (const float*)d_in[2];
    const float* W_hh  = (const float*)d_in[3];
    const float* b_ih  = (const float*)d_in[4];
    const float* b_hh  = (const float*)d_in[5];
    const float* mW1   = (const float*)d_in[6];
    const float* mb1   = (const float*)d_in[7];
    const float* mW2   = (const float*)d_in[8];
    const float* mb2   = (const float*)d_in[9];
    const float* Wg    = (const float*)d_in[10];
    const float* bg    = (const float*)d_in[11];
    const float* Wg2   = (const float*)d_in[12];
    const float* bg2   = (const float*)d_in[13];
    const float* Wl    = (const float*)d_in[14];
    const float* bl    = (const float*)d_in[15];
    const float* We_ih = (const float*)d_in[16];
    const float* We_hh = (const float*)d_in[17];
    const float* be_ih = (const float*)d_in[18];
    const float* be_hh = (const float*)d_in[19];
    const float* Wenc  = (const float*)d_in[20];
    const float* benc  = (const float*)d_in[21];

    int B = in_sizes[0] / 48;   // x is [B, 12, 4]
    int grid = (B + THREADS * EPT - 1) / (THREADS * EPT);
    stae_kernel<<<grid, THREADS>>>(
        x, z, W_ih, W_hh, b_ih, b_hh, mW1, mb1, mW2, mb2,
        Wg, bg, Wg2, bg2, Wl, bl, We_ih, We_hh, be_ih, be_hh,
        Wenc, benc, (float*)d_out, B);
}

// round 2
// speedup vs baseline: 1.1508x; 1.1508x over previous
#include <cuda_runtime.h>

#define THREADS 64
#define EPT 2   // batch elements per thread, packed into f32x2

typedef unsigned long long u64;

__device__ __forceinline__ u64 pk(float lo, float hi) {
    u64 r; asm("mov.b64 %0,{%1,%2};" : "=l"(r) : "f"(lo), "f"(hi)); return r;
}
__device__ __forceinline__ void upk(u64 v, float& lo, float& hi) {
    asm("mov.b64 {%0,%1},%2;" : "=f"(lo), "=f"(hi) : "l"(v));
}
__device__ __forceinline__ u64 ffma2(u64 a, u64 b, u64 c) {
    u64 d; asm("fma.rn.f32x2 %0,%1,%2,%3;" : "=l"(d) : "l"(a), "l"(b), "l"(c)); return d;
}
__device__ __forceinline__ u64 add2(u64 a, u64 b) {
    u64 d; asm("add.rn.f32x2 %0,%1,%2;" : "=l"(d) : "l"(a), "l"(b)); return d;
}

__device__ __forceinline__ float sigm(float x) {
    return __fdividef(1.0f, 1.0f + __expf(-x));
}
__device__ __forceinline__ float tanh_(float x) {
    return __fdividef(2.0f, 1.0f + __expf(-2.0f * x)) - 1.0f;
}

struct __align__(16) SW {
    u64 xsh[48 * THREADS];  // staged x pairs: [value k][tid]
    u64 Wih2[256];          // main LSTM input weights, dup pairs [64 rows][4]
    u64 Whh2[1024];         // main LSTM hidden weights, dup pairs [64 rows][16]
    u64 Weih2[256];         // encoder LSTM input weights
    u64 Wehh2[1024];        // encoder LSTM hidden weights
    u64 Bm2[64];            // (b_ih+b_hh) dup
    u64 Be2[64];            // (be_ih+be_hh) dup
    u64 Wl2[156];           // linear layer weights dup [12][13]
    u64 Bl2[12];            // bl dup
    u64 g2[8];              // Wg[0..2],bg,Wg2[0..2],bg2 dup
    float W1[128];          // mlp layer1 (scalar path)
    float W2[32];
    float Wenc[64];
    float B1[8];
    float B2m[4];
    float Benc[4];
};

// One packed LSTM cell step (2 batch elements / thread).
__device__ __forceinline__ void cell2p(
    const u64* __restrict__ wi,    // [64][4] dup pairs
    const u64* __restrict__ wh,    // [64][16] dup pairs
    const u64* __restrict__ bias,  // [64] dup pairs
    const u64 (&za)[4],
    u64 (&h)[16], float (&c0)[16], float (&c1)[16])
{
    u64 hn[16];
#pragma unroll 4
    for (int u = 0; u < 16; u++) {
        u64 a0 = bias[u], a1 = bias[u + 16], a2 = bias[u + 32], a3 = bias[u + 48];
#pragma unroll
        for (int j = 0; j < 4; j++) {
            a0 = ffma2(za[j], wi[u * 4 + j], a0);
            a1 = ffma2(za[j], wi[(u + 16) * 4 + j], a1);
            a2 = ffma2(za[j], wi[(u + 32) * 4 + j], a2);
            a3 = ffma2(za[j], wi[(u + 48) * 4 + j], a3);
        }
#pragma unroll
        for (int k = 0; k < 16; k++) {
            a0 = ffma2(h[k], wh[u * 16 + k], a0);
            a1 = ffma2(h[k], wh[(u + 16) * 16 + k], a1);
            a2 = ffma2(h[k], wh[(u + 32) * 16 + k], a2);
            a3 = ffma2(h[k], wh[(u + 48) * 16 + k], a3);
        }
        float i0, i1, f0, f1, g0, g1, o0, o1;
        upk(a0, i0, i1); upk(a1, f0, f1); upk(a2, g0, g1); upk(a3, o0, o1);
        c0[u] = sigm(f0) * c0[u] + sigm(i0) * tanh_(g0);
        c1[u] = sigm(f1) * c1[u] + sigm(i1) * tanh_(g1);
        hn[u] = pk(sigm(o0) * tanh_(c0[u]), sigm(o1) * tanh_(c1[u]));
    }
#pragma unroll
    for (int k = 0; k < 16; k++) h[k] = hn[k];
}

__global__ void __launch_bounds__(THREADS, 4) stae_kernel(
    const float* __restrict__ x, const float* __restrict__ z,
    const float* __restrict__ W_ih, const float* __restrict__ W_hh,
    const float* __restrict__ b_ih, const float* __restrict__ b_hh,
    const float* __restrict__ mW1, const float* __restrict__ mb1,
    const float* __restrict__ mW2, const float* __restrict__ mb2,
    const float* __restrict__ Wg, const float* __restrict__ bg,
    const float* __restrict__ Wg2, const float* __restrict__ bg2,
    const float* __restrict__ Wl, const float* __restrict__ bl,
    const float* __restrict__ We_ih, const float* __restrict__ We_hh,
    const float* __restrict__ be_ih, const float* __restrict__ be_hh,
    const float* __restrict__ Wenc, const float* __restrict__ benc,
    float* __restrict__ out, int B)
{
    __shared__ SW s;
    const int tid = threadIdx.x;

    for (int i = tid; i < 256; i += THREADS) {
        s.Wih2[i] = pk(W_ih[i], W_ih[i]);
        s.Weih2[i] = pk(We_ih[i], We_ih[i]);
    }
    for (int i = tid; i < 1024; i += THREADS) {
        s.Whh2[i] = pk(W_hh[i], W_hh[i]);
        s.Wehh2[i] = pk(We_hh[i], We_hh[i]);
    }
    {
        float bm = b_ih[tid] + b_hh[tid];
        float be = be_ih[tid] + be_hh[tid];
        s.Bm2[tid] = pk(bm, bm);
        s.Be2[tid] = pk(be, be);
        s.Wenc[tid] = Wenc[tid];
    }
    for (int i = tid; i < 156; i += THREADS) s.Wl2[i] = pk(Wl[i], Wl[i]);
    for (int i = tid; i < 128; i += THREADS) s.W1[i] = mW1[i];
    if (tid < 32) s.W2[tid] = mW2[tid];
    if (tid < 12) s.Bl2[tid] = pk(bl[tid], bl[tid]);
    if (tid < 8)  s.B1[tid] = mb1[tid];
    if (tid < 4)  { s.B2m[tid] = mb2[tid]; s.Benc[tid] = benc[tid]; }
    if (tid < 3)  { s.g2[tid] = pk(Wg[tid], Wg[tid]); s.g2[4 + tid] = pk(Wg2[tid], Wg2[tid]); }
    if (tid == 3) { s.g2[3] = pk(bg[0], bg[0]); s.g2[7] = pk(bg2[0], bg2[0]); }
    __syncthreads();

    const int b0 = blockIdx.x * (THREADS * EPT) + tid;
    if (b0 >= B) return;
    const int b1 = b0 + THREADS;
    const int b1c = (b1 < B) ? b1 : b0;

    const float* zb0 = z + (size_t)b0 * 48;
    const float* zb1 = z + (size_t)b1c * 48;

    u64 h[16];
    float c0[16], c1[16];
#pragma unroll
    for (int k = 0; k < 16; k++) { h[k] = 0ull; c0[k] = 0.f; c1[k] = 0.f; }

    // ---------------- main LSTM over z (only last h needed) ----------------
    {
        float4 z0 = *(const float4*)zb0;
        float4 z1 = *(const float4*)zb1;
        for (int t = 0; t < 12; t++) {
            float4 z0n, z1n;
            if (t < 11) {
                z0n = *(const float4*)(zb0 + (t + 1) * 4);
                z1n = *(const float4*)(zb1 + (t + 1) * 4);
            }
            u64 za[4] = { pk(z0.x, z1.x), pk(z0.y, z1.y), pk(z0.z, z1.z), pk(z0.w, z1.w) };
            cell2p(s.Wih2, s.Whh2, s.Bm2, za, h, c0, c1);
            z0 = z0n; z1 = z1n;
        }
    }

    // ---------------- middle: mlp -> gcn2 per element; stage x into SMEM -------
    u64* xp = s.xsh + tid;   // stride THREADS between values
    u64 mg[4];
    {
        float hs0[16], hs1[16];
#pragma unroll
        for (int k = 0; k < 16; k++) upk(h[k], hs0[k], hs1[k]);

        float mgv[2][4];
#pragma unroll
        for (int e = 0; e < 2; e++) {
            const float* hh = (e == 0) ? hs0 : hs1;
            float m1[8];
#pragma unroll
            for (int j = 0; j < 8; j++) {
                float a = s.B1[j];
#pragma unroll
                for (int k = 0; k < 16; k++) a += hh[k] * s.W1[j * 16 + k];
                m1[j] = fmaxf(a, 0.f);
            }
            float mo[4];
#pragma unroll
            for (int n = 0; n < 4; n++) {
                float a = s.B2m[n];
#pragma unroll
                for (int j = 0; j < 8; j++) a += m1[j] * s.W2[n * 8 + j];
                mo[n] = a;
            }
            // GCN2 on mlp output (path graph 0-1-2-3)
            float x1_0 = mo[1], x1_1 = mo[0] + mo[2], x1_2 = mo[1] + mo[3], x1_3 = mo[2];
            float x2_0 = x1_1, x2_1 = x1_0 + x1_2, x2_2 = x1_1 + x1_3, x2_3 = x1_2;
            float w0, w1d, w2, bb, dum;
            upk(s.g2[4], w0, dum); upk(s.g2[5], w1d, dum);
            upk(s.g2[6], w2, dum); upk(s.g2[7], bb, dum);
            mgv[e][0] = w0 * mo[0] + w1d * x1_0 + w2 * x2_0 + bb;
            mgv[e][1] = w0 * mo[1] + w1d * x1_1 + w2 * x2_1 + bb;
            mgv[e][2] = w0 * mo[2] + w1d * x1_2 + w2 * x2_2 + bb;
            mgv[e][3] = w0 * mo[3] + w1d * x1_3 + w2 * x2_3 + bb;
        }
#pragma unroll
        for (int n = 0; n < 4; n++) mg[n] = pk(mgv[0][n], mgv[1][n]);

        // stage x rows (flat reshape order) as packed pairs in SMEM
        const float* xb0 = x + (size_t)b0 * 48;
        const float* xb1 = x + (size_t)b1c * 48;
#pragma unroll
        for (int q = 0; q < 12; q++) {
            float4 v0 = *(const float4*)(xb0 + q * 4);
            float4 v1 = *(const float4*)(xb1 + q * 4);
            xp[(q * 4 + 0) * THREADS] = pk(v0.x, v1.x);
            xp[(q * 4 + 1) * THREADS] = pk(v0.y, v1.y);
            xp[(q * 4 + 2) * THREADS] = pk(v0.z, v1.z);
            xp[(q * 4 + 3) * THREADS] = pk(v0.w, v1.w);
        }
    }

    // ---------------- encoder LSTM over en = gcn(x_col) + gcn2(v_col) ----------
#pragma unroll
    for (int k = 0; k < 16; k++) { h[k] = 0ull; c0[k] = 0.f; c1[k] = 0.f; }

    const u64 gw0 = s.g2[0], gw1 = s.g2[1], gw2 = s.g2[2];
    const u64 qw0 = s.g2[4], qw1 = s.g2[5], qw2 = s.g2[6];
    u64 gqb;  // (bg + bg2) dup
    {
        float a, b_, d;
        upk(s.g2[3], a, d); upk(s.g2[7], b_, d);
        gqb = pk(a + b_, a + b_);
    }

    for (int t = 0; t < 12; t++) {
        // x column t  (x_r[n][t] = flat[n*12+t])
        u64 xc[4];
#pragma unroll
        for (int n = 0; n < 4; n++) xc[n] = xp[(n * 12 + t) * THREADS];

        // v_out column t, recomputed: vc[n] = bl[t] + mg[n]*Wl[t][12] + sum_k x[n][k]*Wl[t][k]
        u64 vc[4];
#pragma unroll
        for (int n = 0; n < 4; n++) {
            u64 a = ffma2(mg[n], s.Wl2[t * 13 + 12], s.Bl2[t]);
#pragma unroll
            for (int k = 0; k < 12; k++)
                a = ffma2(xp[(n * 12 + k) * THREADS], s.Wl2[t * 13 + k], a);
            vc[n] = a;
        }

        // diffusion on both columns (path graph)
        u64 a1[4], a2[4], d1[4], d2[4];
        a1[0] = xc[1]; a1[1] = add2(xc[0], xc[2]); a1[2] = add2(xc[1], xc[3]); a1[3] = xc[2];
        a2[0] = a1[1]; a2[1] = add2(a1[0], a1[2]); a2[2] = add2(a1[1], a1[3]); a2[3] = a1[2];
        d1[0] = vc[1]; d1[1] = add2(vc[0], vc[2]); d1[2] = add2(vc[1], vc[3]); d1[3] = vc[2];
        d2[0] = d1[1]; d2[1] = add2(d1[0], d1[2]); d2[2] = add2(d1[1], d1[3]); d2[3] = d1[2];

        u64 en[4];
#pragma unroll
        for (int n = 0; n < 4; n++) {
            u64 a = ffma2(gw0, xc[n], gqb);
            a = ffma2(gw1, a1[n], a);
            a = ffma2(gw2, a2[n], a);
            a = ffma2(qw0, vc[n], a);
            a = ffma2(qw1, d1[n], a);
            en[n] = ffma2(qw2, d2[n], a);
        }
        cell2p(s.Weih2, s.Wehh2, s.Be2, en, h, c0, c1);
    }

    // ---------------- final projection + broadcast write -----------------------
    float lp0[4], lp1[4];
    {
        float hs0[16], hs1[16];
#pragma unroll
        for (int k = 0; k < 16; k++) upk(h[k], hs0[k], hs1[k]);
#pragma unroll
        for (int n = 0; n < 4; n++) {
            float a0 = s.Benc[n], a1_ = s.Benc[n];
#pragma unroll
            for (int k = 0; k < 16; k++) {
                a0 += hs0[k] * s.Wenc[n * 16 + k];
                a1_ += hs1[k] * s.Wenc[n * 16 + k];
            }
            lp0[n] = a0; lp1[n] = a1_;
        }
    }

    {
        float4* o0 = (float4*)(out + (size_t)b0 * 48);
#pragma unroll
        for (int j = 0; j < 12; j++) {
            float v = lp0[j / 3];
            o0[j] = make_float4(v, v, v, v);
        }
        if (b1 < B) {
            float4* o1 = (float4*)(out + (size_t)b1 * 48);
#pragma unroll
            for (int j = 0; j < 12; j++) {
                float v = lp1[j / 3];
                o1[j] = make_float4(v, v, v, v);
            }
        }
    }
}

extern "C" void kernel_launch(void* const* d_in, const int* in_sizes, int n_in,
                              void* d_out, int out_size)
{
    const float* x     = (const float*)d_in[0];
    const float* z     = (const float*)d_in[1];
    const float* W_ih  = (const float*)d_in[2];
    const float* W_hh  = (const float*)d_in[3];
    const float* b_ih  = (const float*)d_in[4];
    const float* b_hh  = (const float*)d_in[5];
    const float* mW1   = (const float*)d_in[6];
    const float* mb1   = (const float*)d_in[7];
    const float* mW2   = (const float*)d_in[8];
    const float* mb2   = (const float*)d_in[9];
    const float* Wg    = (const float*)d_in[10];
    const float* bg    = (const float*)d_in[11];
    const float* Wg2   = (const float*)d_in[12];
    const float* bg2   = (const float*)d_in[13];
    const float* Wl    = (const float*)d_in[14];
    const float* bl    = (const float*)d_in[15];
    const float* We_ih = (const float*)d_in[16];
    const float* We_hh = (const float*)d_in[17];
    const float* be_ih = (const float*)d_in[18];
    const float* be_hh = (const float*)d_in[19];
    const float* Wenc  = (const float*)d_in[20];
    const float* benc  = (const float*)d_in[21];

    int B = in_sizes[0] / 48;   // x is [B, 12, 4]
    int grid = (B + THREADS * EPT - 1) / (THREADS * EPT);
    stae_kernel<<<grid, THREADS>>>(
        x, z, W_ih, W_hh, b_ih, b_hh, mW1, mb1, mW2, mb2,
        Wg, bg, Wg2, bg2, Wl, bl, We_ih, We_hh, be_ih, be_hh,
        Wenc, benc, (float*)d_out, B);
}

// round 4
// speedup vs baseline: 1.2599x; 1.0948x over previous
#include <cuda_runtime.h>

#define THREADS 64
#define EPT 2   // batch elements per thread, packed into f32x2

typedef unsigned long long u64;

__device__ __forceinline__ u64 pk(float lo, float hi) {
    u64 r; asm("mov.b64 %0,{%1,%2};" : "=l"(r) : "f"(lo), "f"(hi)); return r;
}
__device__ __forceinline__ void upk(u64 v, float& lo, float& hi) {
    asm("mov.b64 {%0,%1},%2;" : "=f"(lo), "=f"(hi) : "l"(v));
}
__device__ __forceinline__ u64 ffma2(u64 a, u64 b, u64 c) {
    u64 d; asm("fma.rn.f32x2 %0,%1,%2,%3;" : "=l"(d) : "l"(a), "l"(b), "l"(c)); return d;
}
__device__ __forceinline__ u64 add2(u64 a, u64 b) {
    u64 d; asm("add.rn.f32x2 %0,%1,%2;" : "=l"(d) : "l"(a), "l"(b)); return d;
}

// MUFU.TANH-based activations: 1 MUFU per evaluation.
__device__ __forceinline__ float tanha(float x) {
    float y; asm("tanh.approx.f32 %0,%1;" : "=f"(y) : "f"(x)); return y;
}
__device__ __forceinline__ float sigm(float x) {
    return fmaf(tanha(0.5f * x), 0.5f, 0.5f);
}

struct __align__(16) SW {
    u64 xsh[48 * THREADS];  // staged x pairs: [value k][tid]
    u64 Wih2[256];          // main LSTM input weights, dup pairs [64 rows][4]
    u64 Whh2[1024];         // main LSTM hidden weights, dup pairs [64 rows][16]
    u64 Weih2[256];         // encoder LSTM input weights
    u64 Wehh2[1024];        // encoder LSTM hidden weights
    u64 Bm2[64];            // (b_ih+b_hh) dup
    u64 Be2[64];            // (be_ih+be_hh) dup
    u64 Wl2[12 * 16];       // linear layer weights dup, padded rows (13 used of 16)
    u64 Bl2[12];            // bl dup
    u64 g2[8];              // Wg[0..2],bg,Wg2[0..2],bg2 dup
    float W1[128];          // mlp layer1 (scalar path)
    float W2[32];
    float Wenc[64];
    float B1[8];
    float B2m[4];
    float Benc[4];
};

// One packed LSTM cell step (2 batch elements / thread), LDS.128 weight loads.
__device__ __forceinline__ void cell2p(
    const u64* __restrict__ wi,    // [64][4] dup pairs
    const u64* __restrict__ wh,    // [64][16] dup pairs
    const u64* __restrict__ bias,  // [64] dup pairs
    const u64 (&za)[4],
    u64 (&h)[16], float (&c0)[16], float (&c1)[16])
{
    const ulonglong2* wi2 = (const ulonglong2*)wi;
    const ulonglong2* wh2 = (const ulonglong2*)wh;
    u64 hn[16];
#pragma unroll 4
    for (int u = 0; u < 16; u++) {
        u64 a0 = bias[u], a1 = bias[u + 16], a2 = bias[u + 32], a3 = bias[u + 48];
#pragma unroll
        for (int m = 0; m < 2; m++) {
            ulonglong2 w0 = wi2[u * 2 + m];
            ulonglong2 w1 = wi2[(u + 16) * 2 + m];
            ulonglong2 w2 = wi2[(u + 32) * 2 + m];
            ulonglong2 w3 = wi2[(u + 48) * 2 + m];
            a0 = ffma2(za[2 * m], w0.x, a0); a0 = ffma2(za[2 * m + 1], w0.y, a0);
            a1 = ffma2(za[2 * m], w1.x, a1); a1 = ffma2(za[2 * m + 1], w1.y, a1);
            a2 = ffma2(za[2 * m], w2.x, a2); a2 = ffma2(za[2 * m + 1], w2.y, a2);
            a3 = ffma2(za[2 * m], w3.x, a3); a3 = ffma2(za[2 * m + 1], w3.y, a3);
        }
#pragma unroll
        for (int m = 0; m < 8; m++) {
            ulonglong2 w0 = wh2[u * 8 + m];
            ulonglong2 w1 = wh2[(u + 16) * 8 + m];
            ulonglong2 w2 = wh2[(u + 32) * 8 + m];
            ulonglong2 w3 = wh2[(u + 48) * 8 + m];
            a0 = ffma2(h[2 * m], w0.x, a0); a0 = ffma2(h[2 * m + 1], w0.y, a0);
            a1 = ffma2(h[2 * m], w1.x, a1); a1 = ffma2(h[2 * m + 1], w1.y, a1);
            a2 = ffma2(h[2 * m], w2.x, a2); a2 = ffma2(h[2 * m + 1], w2.y, a2);
            a3 = ffma2(h[2 * m], w3.x, a3); a3 = ffma2(h[2 * m + 1], w3.y, a3);
        }
        float i0, i1, f0, f1, g0, g1, o0, o1;
        upk(a0, i0, i1); upk(a1, f0, f1); upk(a2, g0, g1); upk(a3, o0, o1);
        c0[u] = sigm(f0) * c0[u] + sigm(i0) * tanha(g0);
        c1[u] = sigm(f1) * c1[u] + sigm(i1) * tanha(g1);
        hn[u] = pk(sigm(o0) * tanha(c0[u]), sigm(o1) * tanha(c1[u]));
    }
#pragma unroll
    for (int k = 0; k < 16; k++) h[k] = hn[k];
}

__global__ void __launch_bounds__(THREADS, 4) stae_kernel(
    const float* __restrict__ x, const float* __restrict__ z,
    const float* __restrict__ W_ih, const float* __restrict__ W_hh,
    const float* __restrict__ b_ih, const float* __restrict__ b_hh,
    const float* __restrict__ mW1, const float* __restrict__ mb1,
    const float* __restrict__ mW2, const float* __restrict__ mb2,
    const float* __restrict__ Wg, const float* __restrict__ bg,
    const float* __restrict__ Wg2, const float* __restrict__ bg2,
    const float* __restrict__ Wl, const float* __restrict__ bl,
    const float* __restrict__ We_ih, const float* __restrict__ We_hh,
    const float* __restrict__ be_ih, const float* __restrict__ be_hh,
    const float* __restrict__ Wenc, const float* __restrict__ benc,
    float* __restrict__ out, int B)
{
    __shared__ SW s;
    const int tid = threadIdx.x;

    for (int i = tid; i < 256; i += THREADS) {
        s.Wih2[i] = pk(W_ih[i], W_ih[i]);
        s.Weih2[i] = pk(We_ih[i], We_ih[i]);
    }
    for (int i = tid; i < 1024; i += THREADS) {
        s.Whh2[i] = pk(W_hh[i], W_hh[i]);
        s.Wehh2[i] = pk(We_hh[i], We_hh[i]);
    }
    {
        float bm = b_ih[tid] + b_hh[tid];
        float be = be_ih[tid] + be_hh[tid];
        s.Bm2[tid] = pk(bm, bm);
        s.Be2[tid] = pk(be, be);
        s.Wenc[tid] = Wenc[tid];
    }
    for (int i = tid; i < 156; i += THREADS) {
        int r = i / 13, cidx = i % 13;
        s.Wl2[r * 16 + cidx] = pk(Wl[i], Wl[i]);
    }
    for (int i = tid; i < 128; i += THREADS) s.W1[i] = mW1[i];
    if (tid < 32) s.W2[tid] = mW2[tid];
    if (tid < 12) s.Bl2[tid] = pk(bl[tid], bl[tid]);
    if (tid < 8)  s.B1[tid] = mb1[tid];
    if (tid < 4)  { s.B2m[tid] = mb2[tid]; s.Benc[tid] = benc[tid]; }
    if (tid < 3)  { s.g2[tid] = pk(Wg[tid], Wg[tid]); s.g2[4 + tid] = pk(Wg2[tid], Wg2[tid]); }
    if (tid == 3) { s.g2[3] = pk(bg[0], bg[0]); s.g2[7] = pk(bg2[0], bg2[0]); }
    __syncthreads();

    const int b0 = blockIdx.x * (THREADS * EPT) + tid;
    if (b0 >= B) return;
    const int b1 = b0 + THREADS;
    const int b1c = (b1 < B) ? b1 : b0;

    const float* zb0 = z + (size_t)b0 * 48;
    const float* zb1 = z + (size_t)b1c * 48;

    u64 h[16];
    float c0[16], c1[16];
#pragma unroll
    for (int k = 0; k < 16; k++) { h[k] = 0ull; c0[k] = 0.f; c1[k] = 0.f; }

    // ---------------- main LSTM over z (only last h needed) ----------------
    {
        float4 z0 = *(const float4*)zb0;
        float4 z1 = *(const float4*)zb1;
        for (int t = 0; t < 12; t++) {
            float4 z0n, z1n;
            if (t < 11) {
                z0n = *(const float4*)(zb0 + (t + 1) * 4);
                z1n = *(const float4*)(zb1 + (t + 1) * 4);
            }
            u64 za[4] = { pk(z0.x, z1.x), pk(z0.y, z1.y), pk(z0.z, z1.z), pk(z0.w, z1.w) };
            cell2p(s.Wih2, s.Whh2, s.Bm2, za, h, c0, c1);
            z0 = z0n; z1 = z1n;
        }
    }

    // ---------------- middle: mlp -> gcn2 per element; stage x into SMEM -------
    u64* xp = s.xsh + tid;   // stride THREADS between values
    u64 mg[4];
    {
        float hs0[16], hs1[16];
#pragma unroll
        for (int k = 0; k < 16; k++) upk(h[k], hs0[k], hs1[k]);

        float mgv[2][4];
#pragma unroll
        for (int e = 0; e < 2; e++) {
            const float* hh = (e == 0) ? hs0 : hs1;
            float m1[8];
#pragma unroll
            for (int j = 0; j < 8; j++) {
                float a = s.B1[j];
#pragma unroll
                for (int k = 0; k < 16; k++) a += hh[k] * s.W1[j * 16 + k];
                m1[j] = fmaxf(a, 0.f);
            }
            float mo[4];
#pragma unroll
            for (int n = 0; n < 4; n++) {
                float a = s.B2m[n];
#pragma unroll
                for (int j = 0; j < 8; j++) a += m1[j] * s.W2[n * 8 + j];
                mo[n] = a;
            }
            // GCN2 on mlp output (path graph 0-1-2-3)
            float x1_0 = mo[1], x1_1 = mo[0] + mo[2], x1_2 = mo[1] + mo[3], x1_3 = mo[2];
            float x2_0 = x1_1, x2_1 = x1_0 + x1_2, x2_2 = x1_1 + x1_3, x2_3 = x1_2;
            float w0, w1d, w2, bb, dum;
            upk(s.g2[4], w0, dum); upk(s.g2[5], w1d, dum);
            upk(s.g2[6], w2, dum); upk(s.g2[7], bb, dum);
            mgv[e][0] = w0 * mo[0] + w1d * x1_0 + w2 * x2_0 + bb;
            mgv[e][1] = w0 * mo[1] + w1d * x1_1 + w2 * x2_1 + bb;
            mgv[e][2] = w0 * mo[2] + w1d * x1_2 + w2 * x2_2 + bb;
            mgv[e][3] = w0 * mo[3] + w1d * x1_3 + w2 * x2_3 + bb;
        }
#pragma unroll
        for (int n = 0; n < 4; n++) mg[n] = pk(mgv[0][n], mgv[1][n]);

        // stage x rows (flat reshape order) as packed pairs in SMEM
        const float* xb0 = x + (size_t)b0 * 48;
        const float* xb1 = x + (size_t)b1c * 48;
#pragma unroll
        for (int q = 0; q < 12; q++) {
            float4 v0 = *(const float4*)(xb0 + q * 4);
            float4 v1 = *(const float4*)(xb1 + q * 4);
            xp[(q * 4 + 0) * THREADS] = pk(v0.x, v1.x);
            xp[(q * 4 + 1) * THREADS] = pk(v0.y, v1.y);
            xp[(q * 4 + 2) * THREADS] = pk(v0.z, v1.z);
            xp[(q * 4 + 3) * THREADS] = pk(v0.w, v1.w);
        }
    }

    // ---------------- encoder LSTM over en = gcn(x_col) + gcn2(v_col) ----------
#pragma unroll
    for (int k = 0; k < 16; k++) { h[k] = 0ull; c0[k] = 0.f; c1[k] = 0.f; }

    const u64 gw0 = s.g2[0], gw1 = s.g2[1], gw2 = s.g2[2];
    const u64 qw0 = s.g2[4], qw1 = s.g2[5], qw2 = s.g2[6];
    u64 gqb;  // (bg + bg2) dup
    {
        float a, b_, d;
        upk(s.g2[3], a, d); upk(s.g2[7], b_, d);
        gqb = pk(a + b_, a + b_);
    }

    for (int t = 0; t < 12; t++) {
        // x column t  (x_r[n][t] = flat[n*12+t])
        u64 xc[4];
#pragma unroll
        for (int n = 0; n < 4; n++) xc[n] = xp[(n * 12 + t) * THREADS];

        // v_out column t, recomputed with vectorized weight loads:
        // vc[n] = bl[t] + mg[n]*Wl[t][12] + sum_k x[n][k]*Wl[t][k]
        const ulonglong2* wlr = (const ulonglong2*)&s.Wl2[t * 16];
        const u64 wl12 = s.Wl2[t * 16 + 12];
        u64 vc[4];
#pragma unroll
        for (int n = 0; n < 4; n++) {
            u64 a = ffma2(mg[n], wl12, s.Bl2[t]);
#pragma unroll
            for (int m = 0; m < 6; m++) {
                ulonglong2 w = wlr[m];
                a = ffma2(xp[(n * 12 + 2 * m) * THREADS], w.x, a);
                a = ffma2(xp[(n * 12 + 2 * m + 1) * THREADS], w.y, a);
            }
            vc[n] = a;
        }

        // diffusion on both columns (path graph)
        u64 a1[4], a2[4], d1[4], d2[4];
        a1[0] = xc[1]; a1[1] = add2(xc[0], xc[2]); a1[2] = add2(xc[1], xc[3]); a1[3] = xc[2];
        a2[0] = a1[1]; a2[1] = add2(a1[0], a1[2]); a2[2] = add2(a1[1], a1[3]); a2[3] = a1[2];
        d1[0] = vc[1]; d1[1] = add2(vc[0], vc[2]); d1[2] = add2(vc[1], vc[3]); d1[3] = vc[2];
        d2[0] = d1[1]; d2[1] = add2(d1[0], d1[2]); d2[2] = add2(d1[1], d1[3]); d2[3] = d1[2];

        u64 en[4];
#pragma unroll
        for (int n = 0; n < 4; n++) {
            u64 a = ffma2(gw0, xc[n], gqb);
            a = ffma2(gw1, a1[n], a);
            a = ffma2(gw2, a2[n], a);
            a = ffma2(qw0, vc[n], a);
            a = ffma2(qw1, d1[n], a);
            en[n] = ffma2(qw2, d2[n], a);
        }
        cell2p(s.Weih2, s.Wehh2, s.Be2, en, h, c0, c1);
    }

    // ---------------- final projection + broadcast write -----------------------
    float lp0[4], lp1[4];
    {
        float hs0[16], hs1[16];
#pragma unroll
        for (int k = 0; k < 16; k++) upk(h[k], hs0[k], hs1[k]);
#pragma unroll
        for (int n = 0; n < 4; n++) {
            float a0 = s.Benc[n], a1_ = s.Benc[n];
#pragma unroll
            for (int k = 0; k < 16; k++) {
                a0 += hs0[k] * s.Wenc[n * 16 + k];
                a1_ += hs1[k] * s.Wenc[n * 16 + k];
            }
            lp0[n] = a0; lp1[n] = a1_;
        }
    }

    {
        float4* o0 = (float4*)(out + (size_t)b0 * 48);
#pragma unroll
        for (int j = 0; j < 12; j++) {
            float v = lp0[j / 3];
            o0[j] = make_float4(v, v, v, v);
        }
        if (b1 < B) {
            float4* o1 = (float4*)(out + (size_t)b1 * 48);
#pragma unroll
            for (int j = 0; j < 12; j++) {
                float v = lp1[j / 3];
                o1[j] = make_float4(v, v, v, v);
            }
        }
    }
}

extern "C" void kernel_launch(void* const* d_in, const int* in_sizes, int n_in,
                              void* d_out, int out_size)
{
    const float* x     = (const float*)d_in[0];
    const float* z     = (const float*)d_in[1];
    const float* W_ih  = (const float*)d_in[2];
    const float* W_hh  = (const float*)d_in[3];
    const float* b_ih  = (const float*)d_in[4];
    const float* b_hh  = (const float*)d_in[5];
    const float* mW1   = (const float*)d_in[6];
    const float* mb1   = (const float*)d_in[7];
    const float* mW2   = (const float*)d_in[8];
    const float* mb2   = (const float*)d_in[9];
    const float* Wg    = (const float*)d_in[10];
    const float* bg    = (const float*)d_in[11];
    const float* Wg2   = (const float*)d_in[12];
    const float* bg2   = (const float*)d_in[13];
    const float* Wl    = (const float*)d_in[14];
    const float* bl    = (const float*)d_in[15];
    const float* We_ih = (const float*)d_in[16];
    const float* We_hh = (const float*)d_in[17];
    const float* be_ih = (const float*)d_in[18];
    const float* be_hh = (const float*)d_in[19];
    const float* Wenc  = (const float*)d_in[20];
    const float* benc  = (const float*)d_in[21];

    int B = in_sizes[0] / 48;   // x is [B, 12, 4]
    int grid = (B + THREADS * EPT - 1) / (THREADS * EPT);
    stae_kernel<<<grid, THREADS>>>(
        x, z, W_ih, W_hh, b_ih, b_hh, mW1, mb1, mW2, mb2,
        Wg, bg, Wg2, bg2, Wl, bl, We_ih, We_hh, be_ih, be_hh,
        Wenc, benc, (float*)d_out, B);
}

// round 7
// speedup vs baseline: 1.3806x; 1.0958x over previous
#include <cuda_runtime.h>

#define TB 32      // threads per block (main kernel) = 1 warp
#define EPT 4      // batch elements per thread (2 f32x2 packs)
#define MAXB 131072

typedef unsigned long long u64;

// scratch: z transposed [48][B], en staged [48][B]
__device__ float g_zt[(size_t)48 * MAXB];
__device__ float g_en[(size_t)48 * MAXB];

__device__ __forceinline__ u64 pk(float lo, float hi) {
    u64 r; asm("mov.b64 %0,{%1,%2};" : "=l"(r) : "f"(lo), "f"(hi)); return r;
}
__device__ __forceinline__ void upk(u64 v, float& lo, float& hi) {
    asm("mov.b64 {%0,%1},%2;" : "=f"(lo), "=f"(hi) : "l"(v));
}
__device__ __forceinline__ u64 ffma2(u64 a, u64 b, u64 c) {
    u64 d; asm("fma.rn.f32x2 %0,%1,%2,%3;" : "=l"(d) : "l"(a), "l"(b), "l"(c)); return d;
}
__device__ __forceinline__ float tanha(float x) {
    float y; asm("tanh.approx.f32 %0,%1;" : "=f"(y) : "f"(x)); return y;
}
__device__ __forceinline__ float sigm(float x) {
    return fmaf(tanha(0.5f * x), 0.5f, 0.5f);
}

struct __align__(16) SW {
    u64 Wih2[256];    // main LSTM input weights, dup pairs [64 rows][4]
    u64 Whh2[1024];   // main LSTM hidden weights, dup pairs [64 rows][16]
    u64 Weih2[256];   // encoder LSTM input weights
    u64 Wehh2[1024];  // encoder LSTM hidden weights
    u64 Bm2[64];      // (b_ih+b_hh) dup
    u64 Be2[64];      // (be_ih+be_hh) dup
    float Wlf[12 * 16];  // linear layer weights, padded rows (13 used of 16)
    float Blf[12];
    float W1[128];
    float W2[32];
    float Wenc[64];
    float B1[8];
    float B2m[4];
    float Benc[4];
    float gg[8];      // Wg[0..2], bg, Wg2[0..2], bg2
    float lut[128 * 4];  // final per-element projections for cooperative write
};

// One LSTM step for 4 batch elements (2 f32x2 packs). Every weight load
// (LDS.128 = 2 dup-pairs) feeds 4 FFMA2s -> weight bytes amortized 4 ways.
__device__ __forceinline__ void cell4p(
    const u64* __restrict__ wi,    // [64][4] dup pairs
    const u64* __restrict__ wh,    // [64][16] dup pairs
    const u64* __restrict__ bias,  // [64] dup pairs
    const u64 (&za)[4][2], u64 (&h)[16][2], u64 (&c)[16][2])
{
    const ulonglong2* wi2 = (const ulonglong2*)wi;
    const ulonglong2* wh2 = (const ulonglong2*)wh;
    u64 hn[16][2];
#pragma unroll 4
    for (int u = 0; u < 16; u++) {
        u64 A[4][2];
#pragma unroll
        for (int g = 0; g < 4; g++) { u64 b = bias[u + 16 * g]; A[g][0] = b; A[g][1] = b; }
#pragma unroll
        for (int m = 0; m < 2; m++) {
#pragma unroll
            for (int g = 0; g < 4; g++) {
                ulonglong2 w = wi2[(u + 16 * g) * 2 + m];
#pragma unroll
                for (int p = 0; p < 2; p++) {
                    A[g][p] = ffma2(za[2 * m][p], w.x, A[g][p]);
                    A[g][p] = ffma2(za[2 * m + 1][p], w.y, A[g][p]);
                }
            }
        }
#pragma unroll
        for (int m = 0; m < 8; m++) {
#pragma unroll
            for (int g = 0; g < 4; g++) {
                ulonglong2 w = wh2[(u + 16 * g) * 8 + m];
#pragma unroll
                for (int p = 0; p < 2; p++) {
                    A[g][p] = ffma2(h[2 * m][p], w.x, A[g][p]);
                    A[g][p] = ffma2(h[2 * m + 1][p], w.y, A[g][p]);
                }
            }
        }
#pragma unroll
        for (int p = 0; p < 2; p++) {
            float i0, i1, f0, f1, g0, g1, o0, o1, cl, ch;
            upk(A[0][p], i0, i1); upk(A[1][p], f0, f1);
            upk(A[2][p], g0, g1); upk(A[3][p], o0, o1);
            upk(c[u][p], cl, ch);
            cl = sigm(f0) * cl + sigm(i0) * tanha(g0);
            ch = sigm(f1) * ch + sigm(i1) * tanha(g1);
            c[u][p] = pk(cl, ch);
            hn[u][p] = pk(sigm(o0) * tanha(cl), sigm(o1) * tanha(ch));
        }
    }
#pragma unroll
    for (int k = 0; k < 16; k++) { h[k][0] = hn[k][0]; h[k][1] = hn[k][1]; }
}

// Transpose z [B][48] -> g_zt [48][B] so the main kernel's recurrent loads coalesce.
__global__ void zt_kernel(const float* __restrict__ z, int B)
{
    __shared__ float ts[64 * 49];
    const int e0 = blockIdx.x * 64;
    const int cnt = min(64, B - e0);
    const float4* zp = (const float4*)(z + (size_t)e0 * 48);
    for (int i = threadIdx.x; i < 768; i += 256) {
        int base = i * 4;
        int el = base / 48, v = base % 48;
        if (el < cnt) {
            float4 w = zp[i];
            ts[el * 49 + v] = w.x; ts[el * 49 + v + 1] = w.y;
            ts[el * 49 + v + 2] = w.z; ts[el * 49 + v + 3] = w.w;
        }
    }
    __syncthreads();
    for (int i = threadIdx.x; i < 3072; i += 256) {
        int v = i >> 6, el = i & 63;
        if (el < cnt)
            g_zt[(size_t)v * B + e0 + el] = ts[el * 49 + v];
    }
}

__global__ void __launch_bounds__(TB, 8) stae_main(
    const float* __restrict__ x,
    const float* __restrict__ W_ih, const float* __restrict__ W_hh,
    const float* __restrict__ b_ih, const float* __restrict__ b_hh,
    const float* __restrict__ mW1, const float* __restrict__ mb1,
    const float* __restrict__ mW2, const float* __restrict__ mb2,
    const float* __restrict__ Wg, const float* __restrict__ bg,
    const float* __restrict__ Wg2, const float* __restrict__ bg2,
    const float* __restrict__ Wl, const float* __restrict__ bl,
    const float* __restrict__ We_ih, const float* __restrict__ We_hh,
    const float* __restrict__ be_ih, const float* __restrict__ be_hh,
    const float* __restrict__ Wenc, const float* __restrict__ benc,
    float* __restrict__ out, int B)
{
    __shared__ SW s;
    const int tid = threadIdx.x;

    for (int i = tid; i < 256; i += TB) {
        s.Wih2[i] = pk(W_ih[i], W_ih[i]);
        s.Weih2[i] = pk(We_ih[i], We_ih[i]);
    }
    for (int i = tid; i < 1024; i += TB) {
        s.Whh2[i] = pk(W_hh[i], W_hh[i]);
        s.Wehh2[i] = pk(We_hh[i], We_hh[i]);
    }
    for (int i = tid; i < 64; i += TB) {
        s.Bm2[i] = pk(b_ih[i] + b_hh[i], b_ih[i] + b_hh[i]);
        s.Be2[i] = pk(be_ih[i] + be_hh[i], be_ih[i] + be_hh[i]);
        s.Wenc[i] = Wenc[i];
    }
    for (int i = tid; i < 156; i += TB) s.Wlf[(i / 13) * 16 + (i % 13)] = Wl[i];
    for (int i = tid; i < 128; i += TB) s.W1[i] = mW1[i];
    if (tid < 32) s.W2[tid] = mW2[tid];
    if (tid < 12) s.Blf[tid] = bl[tid];
    if (tid < 8)  s.B1[tid] = mb1[tid];
    if (tid < 4)  { s.B2m[tid] = mb2[tid]; s.Benc[tid] = benc[tid]; }
    if (tid < 3)  { s.gg[tid] = Wg[tid]; s.gg[4 + tid] = Wg2[tid]; }
    if (tid == 3) { s.gg[3] = bg[0]; s.gg[7] = bg2[0]; }
    __syncthreads();

    const int warpBase = blockIdx.x * (TB * EPT);   // 128 elements per warp
    const int e0 = warpBase + tid * EPT;            // 4 consecutive elements
    const int e0c = (e0 + EPT <= B) ? e0 : (B > EPT ? B - EPT : 0);  // clamped for vector loads

    u64 h[16][2], c[16][2];
    u64 za[4][2];
#pragma unroll
    for (int k = 0; k < 16; k++) { h[k][0] = h[k][1] = 0ull; c[k][0] = c[k][1] = 0ull; }

    // ---------------- phase 1: main LSTM over z_t (coalesced) ----------------
    {
        float4 zv[4], zn[4];
#pragma unroll
        for (int q = 0; q < 4; q++) zv[q] = *(const float4*)(g_zt + (size_t)q * B + e0c);
#pragma unroll 1
        for (int t = 0; t < 12; t++) {
            if (t < 11) {
#pragma unroll
                for (int q = 0; q < 4; q++)
                    zn[q] = *(const float4*)(g_zt + (size_t)((t + 1) * 4 + q) * B + e0c);
            }
#pragma unroll
            for (int q = 0; q < 4; q++) {
                za[q][0] = pk(zv[q].x, zv[q].y);
                za[q][1] = pk(zv[q].z, zv[q].w);
            }
            cell4p(s.Wih2, s.Whh2, s.Bm2, za, h, c);
#pragma unroll
            for (int q = 0; q < 4; q++) zv[q] = zn[q];
        }
    }

    // ------------- epilogue: per-element mlp -> gcn2 -> v_out -> en ----------
#pragma unroll 1
    for (int j = 0; j < EPT; j++) {
        const int p = j >> 1, hi = j & 1;
        float hs[16];
#pragma unroll
        for (int k = 0; k < 16; k++) {
            float a, b; upk(h[k][p], a, b); hs[k] = hi ? b : a;
        }
        float m1[8];
#pragma unroll
        for (int jj = 0; jj < 8; jj++) {
            float a = s.B1[jj];
#pragma unroll
            for (int k = 0; k < 16; k++) a += hs[k] * s.W1[jj * 16 + k];
            m1[jj] = fmaxf(a, 0.f);
        }
        float mo[4];
#pragma unroll
        for (int n = 0; n < 4; n++) {
            float a = s.B2m[n];
#pragma unroll
            for (int jj = 0; jj < 8; jj++) a += m1[jj] * s.W2[n * 8 + jj];
            mo[n] = a;
        }
        // GCN2 on mlp output (path graph 0-1-2-3)
        float q0 = s.gg[4], q1 = s.gg[5], q2 = s.gg[6], qb = s.gg[7];
        float x1_0 = mo[1], x1_1 = mo[0] + mo[2], x1_2 = mo[1] + mo[3], x1_3 = mo[2];
        float x2_0 = x1_1, x2_1 = x1_0 + x1_2, x2_2 = x1_1 + x1_3, x2_3 = x1_2;
        float mg[4];
        mg[0] = q0 * mo[0] + q1 * x1_0 + q2 * x2_0 + qb;
        mg[1] = q0 * mo[1] + q1 * x1_1 + q2 * x2_1 + qb;
        mg[2] = q0 * mo[2] + q1 * x1_2 + q2 * x2_2 + qb;
        mg[3] = q0 * mo[3] + q1 * x1_3 + q2 * x2_3 + qb;

        const int e = e0c + j;
        float xr[48];
        {
            const float4* xb = (const float4*)(x + (size_t)e * 48);
#pragma unroll
            for (int q = 0; q < 12; q++) {
                float4 v = xb[q];
                xr[q * 4 + 0] = v.x; xr[q * 4 + 1] = v.y;
                xr[q * 4 + 2] = v.z; xr[q * 4 + 3] = v.w;
            }
        }
        const float g0_ = s.gg[0], g1_ = s.gg[1], g2_ = s.gg[2], gb_ = s.gg[3];
        const bool wr = (e0 + j) < B;
#pragma unroll 1
        for (int t = 0; t < 12; t++) {
            float vc[4];
#pragma unroll
            for (int n = 0; n < 4; n++) {
                float a = s.Blf[t] + mg[n] * s.Wlf[t * 16 + 12];
#pragma unroll
                for (int k = 0; k < 12; k++) a += xr[n * 12 + k] * s.Wlf[t * 16 + k];
                vc[n] = a;
            }
            float xc0 = xr[t], xc1 = xr[12 + t], xc2 = xr[24 + t], xc3 = xr[36 + t];
            float a1_0 = xc1, a1_1 = xc0 + xc2, a1_2 = xc1 + xc3, a1_3 = xc2;
            float a2_0 = a1_1, a2_1 = a1_0 + a1_2, a2_2 = a1_1 + a1_3, a2_3 = a1_2;
            float d1_0 = vc[1], d1_1 = vc[0] + vc[2], d1_2 = vc[1] + vc[3], d1_3 = vc[2];
            float d2_0 = d1_1, d2_1 = d1_0 + d1_2, d2_2 = d1_1 + d1_3, d2_3 = d1_2;
            float en0 = g0_ * xc0 + g1_ * a1_0 + g2_ * a2_0 + gb_ + q0 * vc[0] + q1 * d1_0 + q2 * d2_0 + qb;
            float en1 = g0_ * xc1 + g1_ * a1_1 + g2_ * a2_1 + gb_ + q0 * vc[1] + q1 * d1_1 + q2 * d2_1 + qb;
            float en2 = g0_ * xc2 + g1_ * a1_2 + g2_ * a2_2 + gb_ + q0 * vc[2] + q1 * d1_2 + q2 * d2_2 + qb;
            float en3 = g0_ * xc3 + g1_ * a1_3 + g2_ * a2_3 + gb_ + q0 * vc[3] + q1 * d1_3 + q2 * d2_3 + qb;
            if (wr) {
                g_en[(size_t)(0 * 12 + t) * B + e] = en0;
                g_en[(size_t)(1 * 12 + t) * B + e] = en1;
                g_en[(size_t)(2 * 12 + t) * B + e] = en2;
                g_en[(size_t)(3 * 12 + t) * B + e] = en3;
            }
        }
    }

    // ---------------- phase 3: encoder LSTM over en (coalesced) ---------------
#pragma unroll
    for (int k = 0; k < 16; k++) { h[k][0] = h[k][1] = 0ull; c[k][0] = c[k][1] = 0ull; }
    {
        float4 ev[4], en2[4];
#pragma unroll
        for (int n = 0; n < 4; n++) ev[n] = *(const float4*)(g_en + (size_t)(n * 12) * B + e0c);
#pragma unroll 1
        for (int t = 0; t < 12; t++) {
            if (t < 11) {
#pragma unroll
                for (int n = 0; n < 4; n++)
                    en2[n] = *(const float4*)(g_en + (size_t)(n * 12 + t + 1) * B + e0c);
            }
#pragma unroll
            for (int n = 0; n < 4; n++) {
                za[n][0] = pk(ev[n].x, ev[n].y);
                za[n][1] = pk(ev[n].z, ev[n].w);
            }
            cell4p(s.Weih2, s.Wehh2, s.Be2, za, h, c);
#pragma unroll
            for (int n = 0; n < 4; n++) ev[n] = en2[n];
        }
    }

    // ---------------- final projection -> SMEM lut -> cooperative write -------
#pragma unroll 1
    for (int j = 0; j < EPT; j++) {
        const int p = j >> 1, hi = j & 1;
        float hs[16];
#pragma unroll
        for (int k = 0; k < 16; k++) {
            float a, b; upk(h[k][p], a, b); hs[k] = hi ? b : a;
        }
#pragma unroll
        for (int n = 0; n < 4; n++) {
            float a = s.Benc[n];
#pragma unroll
            for (int k = 0; k < 16; k++) a += hs[k] * s.Wenc[n * 16 + k];
            s.lut[(tid * EPT + j) * 4 + n] = a;
        }
    }
    __syncwarp();

    // warp block = 128 rows x 48 floats = 1536 float4s, coalesced
    float4* ob = (float4*)(out + (size_t)warpBase * 48);
#pragma unroll 1
    for (int r = 0; r < 48; r++) {
        int f = r * TB + tid;
        int el = f / 12;          // local element 0..127
        int jj = f % 12;          // float4 index within row
        if (warpBase + el < B) {
            float v = s.lut[el * 4 + jj / 3];
            ob[f] = make_float4(v, v, v, v);
        }
    }
}

extern "C" void kernel_launch(void* const* d_in, const int* in_sizes, int n_in,
                              void* d_out, int out_size)
{
    const float* x     = (const float*)d_in[0];
    const float* z     = (const float*)d_in[1];
    const float* W_ih  = (const float*)d_in[2];
    const float* W_hh  = (const float*)d_in[3];
    const float* b_ih  = (const float*)d_in[4];
    const float* b_hh  = (const float*)d_in[5];
    const float* mW1   = (const float*)d_in[6];
    const float* mb1   = (const float*)d_in[7];
    const float* mW2   = (const float*)d_in[8];
    const float* mb2   = (const float*)d_in[9];
    const float* Wg    = (const float*)d_in[10];
    const float* bg    = (const float*)d_in[11];
    const float* Wg2   = (const float*)d_in[12];
    const float* bg2   = (const float*)d_in[13];
    const float* Wl    = (const float*)d_in[14];
    const float* bl    = (const float*)d_in[15];
    const float* We_ih = (const float*)d_in[16];
    const float* We_hh = (const float*)d_in[17];
    const float* be_ih = (const float*)d_in[18];
    const float* be_hh = (const float*)d_in[19];
    const float* Wenc  = (const float*)d_in[20];
    const float* benc  = (const float*)d_in[21];

    int B = in_sizes[0] / 48;   // x is [B, 12, 4]
    zt_kernel<<<(B + 63) / 64, 256>>>(z, B);
    stae_main<<<(B + TB * EPT - 1) / (TB * EPT), TB>>>(
        x, W_ih, W_hh, b_ih, b_hh, mW1, mb1, mW2, mb2,
        Wg, bg, Wg2, bg2, Wl, bl, We_ih, We_hh, be_ih, be_hh,
        Wenc, benc, (float*)d_out, B);
}